// round 1
// baseline (speedup 1.0000x reference)
#include <cuda_runtime.h>
#include <math.h>

// Problem shape (fixed by setup_inputs)
#define BS     16
#define SLEN   2048
#define DIM    1024
#define M_TOT  (BS * SLEN)   // 32768 rows of states
#define NSPLIT 8             // GEMM N split into 8 blocks of 128

// Scratch (allocation-free rule: __device__ globals)
__device__ float g_eq[BS];                       // tanh(q)@We_q per batch
__device__ float g_ek_part[NSPLIT * M_TOT];      // per-N-split energy partials
__device__ float g_attn_part[16 * BS * DIM];     // per-s-chunk attn partials

// ---------------------------------------------------------------------------
// Kernel A: eq[b] = sum_d tanh(relu(query[b]@Wq + bq)_d) * We_q[d]
// One CTA per batch row. 256 threads, 4 columns each.
// ---------------------------------------------------------------------------
__global__ void __launch_bounds__(256) k_qenergy(
        const float* __restrict__ query, const float* __restrict__ Wq,
        const float* __restrict__ bq,    const float* __restrict__ We) {
    const int b = blockIdx.x;
    const int tid = threadIdx.x;
    __shared__ float qs[DIM];
    for (int v = tid; v < DIM; v += 256) qs[v] = query[b * DIM + v];
    __syncthreads();

    float acc[4] = {0.f, 0.f, 0.f, 0.f};
    for (int v = 0; v < DIM; v++) {
        const float qv = qs[v];
        const float* w = Wq + (size_t)v * DIM + tid;
        acc[0] = fmaf(qv, w[0],   acc[0]);
        acc[1] = fmaf(qv, w[256], acc[1]);
        acc[2] = fmaf(qv, w[512], acc[2]);
        acc[3] = fmaf(qv, w[768], acc[3]);
    }
    float e = 0.f;
    #pragma unroll
    for (int j = 0; j < 4; j++) {
        const int d = tid + 256 * j;
        const float v = fmaxf(acc[j] + bq[d], 0.f);
        e += tanhf(v) * We[d];
    }
    __shared__ float red[256];
    red[tid] = e; __syncthreads();
    for (int s = 128; s > 0; s >>= 1) {
        if (tid < s) red[tid] += red[tid + s];
        __syncthreads();
    }
    if (tid == 0) g_eq[b] = red[0];
}

// ---------------------------------------------------------------------------
// Kernel B (dominant): SGEMM states(32768x1024) @ Wk(1024x1024) with fused
// epilogue  e_part[nsplit][m] = sum_{n in tile} tanh(relu(c + bk[n]))*We_k[n].
// Tile 128x128, BK=8, 256 threads, 8x8 register micro-tile.
// blockIdx.x = n-split (fast) so same-M CTAs share A tiles via L2.
// ---------------------------------------------------------------------------
__global__ void __launch_bounds__(256, 2) k_gemm_energy(
        const float* __restrict__ states, const float* __restrict__ Wk,
        const float* __restrict__ bk,     const float* __restrict__ We_k) {
    const int n_blk = blockIdx.x;   // 0..7
    const int m_blk = blockIdx.y;   // 0..255
    const int tid = threadIdx.x;
    const int tx = tid & 15;
    const int ty = tid >> 4;

    __shared__ float As[8][128];    // As[k][m]
    __shared__ float Bs[8][128];    // Bs[k][n]

    const float* A = states + (size_t)m_blk * 128 * DIM;
    const float* B = Wk + n_blk * 128;

    const int a_m = tid >> 1;             // 0..127
    const int a_k = (tid & 1) * 4;        // 0 or 4
    const int b_k = tid >> 5;             // 0..7
    const int b_n = (tid & 31) * 4;       // 0..124

    float acc[8][8];
    #pragma unroll
    for (int i = 0; i < 8; i++)
        #pragma unroll
        for (int j = 0; j < 8; j++) acc[i][j] = 0.f;

    for (int k0 = 0; k0 < DIM; k0 += 8) {
        const float4 av = *(const float4*)(A + (size_t)a_m * DIM + k0 + a_k);
        As[a_k + 0][a_m] = av.x;
        As[a_k + 1][a_m] = av.y;
        As[a_k + 2][a_m] = av.z;
        As[a_k + 3][a_m] = av.w;
        *(float4*)&Bs[b_k][b_n] =
            *(const float4*)(B + (size_t)(k0 + b_k) * DIM + b_n);
        __syncthreads();

        #pragma unroll
        for (int kk = 0; kk < 8; kk++) {
            float a[8], bb[8];
            *(float4*)&a[0]  = *(const float4*)&As[kk][ty * 8];
            *(float4*)&a[4]  = *(const float4*)&As[kk][ty * 8 + 4];
            *(float4*)&bb[0] = *(const float4*)&Bs[kk][tx * 8];
            *(float4*)&bb[4] = *(const float4*)&Bs[kk][tx * 8 + 4];
            #pragma unroll
            for (int i = 0; i < 8; i++)
                #pragma unroll
                for (int j = 0; j < 8; j++)
                    acc[i][j] = fmaf(a[i], bb[j], acc[i][j]);
        }
        __syncthreads();
    }

    // Fused epilogue: reduce N within tile -> per-row scalar partial
    const int n0 = n_blk * 128 + tx * 8;
    float bkv[8], wev[8];
    #pragma unroll
    for (int j = 0; j < 8; j++) {
        bkv[j] = bk[n0 + j];
        wev[j] = We_k[n0 + j];
    }
    const int m0 = m_blk * 128 + ty * 8;
    #pragma unroll
    for (int i = 0; i < 8; i++) {
        float p = 0.f;
        #pragma unroll
        for (int j = 0; j < 8; j++) {
            const float v = fmaxf(acc[i][j] + bkv[j], 0.f);
            p += tanhf(v) * wev[j];
        }
        // reduce across the 16 tx-lanes sharing this row (width-16 groups)
        #pragma unroll
        for (int off = 8; off > 0; off >>= 1)
            p += __shfl_down_sync(0xffffffffu, p, off, 16);
        if (tx == 0) g_ek_part[n_blk * M_TOT + m0 + i] = p;
    }
}

// ---------------------------------------------------------------------------
// Kernel C: combine partials + softmax over s, write attn_weights to out[0:32768]
// ---------------------------------------------------------------------------
__global__ void __launch_bounds__(256) k_softmax(
        const float* __restrict__ be, float* __restrict__ out_w) {
    const int b = blockIdx.x;
    const int tid = threadIdx.x;
    const float base = g_eq[b] + be[0];

    float e[8];
    float lmax = -1e30f;
    #pragma unroll
    for (int r = 0; r < 8; r++) {
        const int s = r * 256 + tid;
        float v = base;
        #pragma unroll
        for (int p = 0; p < NSPLIT; p++)
            v += g_ek_part[p * M_TOT + b * SLEN + s];
        e[r] = v;
        lmax = fmaxf(lmax, v);
    }
    __shared__ float red[256];
    red[tid] = lmax; __syncthreads();
    for (int s = 128; s > 0; s >>= 1) {
        if (tid < s) red[tid] = fmaxf(red[tid], red[tid + s]);
        __syncthreads();
    }
    const float gmax = red[0];
    __syncthreads();

    float lsum = 0.f;
    #pragma unroll
    for (int r = 0; r < 8; r++) {
        e[r] = expf(e[r] - gmax);
        lsum += e[r];
    }
    red[tid] = lsum; __syncthreads();
    for (int s = 128; s > 0; s >>= 1) {
        if (tid < s) red[tid] += red[tid + s];
        __syncthreads();
    }
    const float inv = 1.f / red[0];
    #pragma unroll
    for (int r = 0; r < 8; r++)
        out_w[b * SLEN + r * 256 + tid] = e[r] * inv;
}

// ---------------------------------------------------------------------------
// Kernel D: attn partials over s-chunks of 128 (deterministic, no atomics)
// ---------------------------------------------------------------------------
__global__ void __launch_bounds__(256) k_attn_part(
        const float* __restrict__ states, const float* __restrict__ w) {
    const int sc = blockIdx.x;   // 0..15 s-chunk
    const int b  = blockIdx.y;   // 0..15 batch
    const int tid = threadIdx.x;
    float acc[4] = {0.f, 0.f, 0.f, 0.f};
    const int s0 = sc * 128;
    for (int sl = 0; sl < 128; sl++) {
        const int s = s0 + sl;
        const float wv = w[b * SLEN + s];
        const float* row = states + (size_t)(b * SLEN + s) * DIM + tid;
        acc[0] = fmaf(wv, row[0],   acc[0]);
        acc[1] = fmaf(wv, row[256], acc[1]);
        acc[2] = fmaf(wv, row[512], acc[2]);
        acc[3] = fmaf(wv, row[768], acc[3]);
    }
    float* dst = g_attn_part + (size_t)(sc * BS + b) * DIM + tid;
    dst[0] = acc[0]; dst[256] = acc[1]; dst[512] = acc[2]; dst[768] = acc[3];
}

// ---------------------------------------------------------------------------
// Kernel E: reduce 16 s-chunk partials -> out[32768 : 32768+16384]
// ---------------------------------------------------------------------------
__global__ void __launch_bounds__(256) k_attn_reduce(float* __restrict__ out_attn) {
    const int idx = blockIdx.x * 256 + threadIdx.x;  // 0..16383 == b*1024 + d
    const int b = idx >> 10;
    const int d = idx & 1023;
    float s = 0.f;
    #pragma unroll
    for (int p = 0; p < 16; p++)
        s += g_attn_part[(size_t)(p * BS + b) * DIM + d];
    out_attn[idx] = s;
}

// ---------------------------------------------------------------------------
extern "C" void kernel_launch(void* const* d_in, const int* in_sizes, int n_in,
                              void* d_out, int out_size) {
    const float* query  = (const float*)d_in[0];   // (16, 1024)
    const float* states = (const float*)d_in[1];   // (16, 2048, 1024)
    const float* Wq     = (const float*)d_in[2];   // (1024, 1024)
    const float* bq     = (const float*)d_in[3];   // (1024,)
    const float* Wk     = (const float*)d_in[4];   // (1024, 1024)
    const float* bk     = (const float*)d_in[5];   // (1024,)
    const float* We     = (const float*)d_in[6];   // (2048,)
    const float* be     = (const float*)d_in[7];   // (1,)

    float* out      = (float*)d_out;
    float* out_w    = out;                 // attn_weights (16, 2048)
    float* out_attn = out + BS * SLEN;     // attn         (16, 1024)

    k_qenergy<<<BS, 256>>>(query, Wq, bq, We);
    k_gemm_energy<<<dim3(NSPLIT, M_TOT / 128), 256>>>(states, Wk, bk, We + DIM);
    k_softmax<<<BS, 256>>>(be, out_w);
    k_attn_part<<<dim3(16, BS), 256>>>(states, out_w);
    k_attn_reduce<<<BS * DIM / 256, 256>>>(out_attn);
}

// round 3
// speedup vs baseline: 1.9708x; 1.9708x over previous
#include <cuda_runtime.h>
#include <cuda_bf16.h>
#include <math.h>
#include <stdint.h>

#define BS     16
#define SLEN   2048
#define DIM    1024
#define M_TOT  (BS * SLEN)   // 32768
#define NSPLIT 8

// ---------------------------------------------------------------------------
// Scratch (__device__ globals; allocation-free rule)
// ---------------------------------------------------------------------------
__device__ __align__(16) __nv_bfloat16 g_wkT_hi[(size_t)DIM * DIM]; // WkT[n][k]
__device__ __align__(16) __nv_bfloat16 g_wkT_lo[(size_t)DIM * DIM];
__device__ float g_ek_part[NSPLIT * M_TOT];
__device__ float g_eq_part[BS * 4];
__device__ __align__(16) float g_attn_part[32 * BS * DIM];

__device__ __forceinline__ uint32_t smem_u32(const void* p) {
    uint32_t a;
    asm("{ .reg .u64 t; cvta.to.shared.u64 t, %1; cvt.u32.u64 %0, t; }"
        : "=r"(a) : "l"(p));
    return a;
}

#define LDMX4(r0, r1, r2, r3, addr)                                          \
    asm volatile("ldmatrix.sync.aligned.m8n8.x4.shared.b16 {%0,%1,%2,%3}, [%4];" \
        : "=r"(r0), "=r"(r1), "=r"(r2), "=r"(r3) : "r"(addr))

#define MMA16816(c, a, b0, b1)                                               \
    asm volatile("mma.sync.aligned.m16n8k16.row.col.f32.bf16.bf16.f32 "      \
        "{%0,%1,%2,%3}, {%4,%5,%6,%7}, {%8,%9}, {%0,%1,%2,%3};"              \
        : "+f"((c)[0]), "+f"((c)[1]), "+f"((c)[2]), "+f"((c)[3])             \
        : "r"((a)[0]), "r"((a)[1]), "r"((a)[2]), "r"((a)[3]),                \
          "r"(b0), "r"(b1))

// ---------------------------------------------------------------------------
// WkT (transpose) + hi/lo split.  WkT[d][v] = Wk[v][d]
// ---------------------------------------------------------------------------
__global__ void __launch_bounds__(256) k_convert_wkT(const float* __restrict__ Wk) {
    __shared__ float tile[32][33];
    const int tx = threadIdx.x, ty = threadIdx.y;        // (32, 8)
    const int v0 = blockIdx.y * 32, d0 = blockIdx.x * 32;
    #pragma unroll
    for (int j = 0; j < 4; j++)
        tile[ty + j * 8][tx] = Wk[(size_t)(v0 + ty + j * 8) * DIM + d0 + tx];
    __syncthreads();
    #pragma unroll
    for (int j = 0; j < 4; j++) {
        const int dy = ty + j * 8;
        const float val = tile[tx][dy];
        const __nv_bfloat16 h = __float2bfloat16(val);
        const __nv_bfloat16 l = __float2bfloat16(val - __bfloat162float(h));
        const size_t o = (size_t)(d0 + dy) * DIM + v0 + tx;
        g_wkT_hi[o] = h;
        g_wkT_lo[o] = l;
    }
}

// ---------------------------------------------------------------------------
// eq partials
// ---------------------------------------------------------------------------
__global__ void __launch_bounds__(256) k_qenergy(
        const float* __restrict__ query, const float* __restrict__ Wq,
        const float* __restrict__ bq,    const float* __restrict__ We) {
    const int b = blockIdx.x, q = blockIdx.y;
    const int tid = threadIdx.x;
    const int col = q * 256 + tid;
    __shared__ float qs[DIM];
    for (int v = tid; v < DIM; v += 256) qs[v] = query[b * DIM + v];
    __syncthreads();
    float acc = 0.f;
    #pragma unroll 4
    for (int v = 0; v < DIM; v++)
        acc = fmaf(qs[v], Wq[(size_t)v * DIM + col], acc);
    const float val = fmaxf(acc + bq[col], 0.f);
    float e = tanhf(val) * We[col];
    __shared__ float red[256];
    red[tid] = e; __syncthreads();
    for (int s = 128; s > 0; s >>= 1) {
        if (tid < s) red[tid] += red[tid + s];
        __syncthreads();
    }
    if (tid == 0) g_eq_part[b * 4 + q] = red[0];
}

// ---------------------------------------------------------------------------
// GEMM via mma.sync bf16 hi/lo split, fused tanh*We epilogue reduction.
// CTA 128(M) x 128(N), K=1024 in 32 slabs of 32, double-buffered.
// smem rows pitched 80B (conflict-free ldmatrix).
// ---------------------------------------------------------------------------
#define TILE_B   10240              // 128 rows * 80B
#define OFF_AH   0
#define OFF_AL   (1 * TILE_B)
#define OFF_BH   (2 * TILE_B)
#define OFF_BL   (3 * TILE_B)
#define BUF_SZ   (4 * TILE_B)       // 40960
#define RED_OFF  (2 * BUF_SZ)       // 81920
#define GEMM_SMEM (RED_OFF + 4 * 128 * 4)   // 83968

struct Stage {
    float4 a[2];
    uint4  bh, bl;
};

__device__ __forceinline__ void ld_stage(
        Stage& st, const float* __restrict__ A,
        const __nv_bfloat16* __restrict__ Bh,
        const __nv_bfloat16* __restrict__ Bl, int k0, int tid) {
    #pragma unroll
    for (int p = 0; p < 2; p++) {
        const int idx = p * 512 + tid;
        const int row = idx >> 3, c4 = idx & 7;
        st.a[p] = *(const float4*)(A + (size_t)row * DIM + k0 + c4 * 4);
    }
    const int row = tid >> 2, seg = tid & 3;
    const size_t g = (size_t)row * DIM + k0 + seg * 8;
    st.bh = *(const uint4*)(Bh + g);
    st.bl = *(const uint4*)(Bl + g);
}

__device__ __forceinline__ void st_stage(const Stage& st, char* smem,
                                         uint32_t bufoff, int tid) {
    #pragma unroll
    for (int p = 0; p < 2; p++) {
        const int idx = p * 512 + tid;
        const int row = idx >> 3, c4 = idx & 7;
        const float4 v = st.a[p];
        __nv_bfloat16 h0 = __float2bfloat16(v.x), h1 = __float2bfloat16(v.y);
        __nv_bfloat16 h2 = __float2bfloat16(v.z), h3 = __float2bfloat16(v.w);
        __nv_bfloat16 l0 = __float2bfloat16(v.x - __bfloat162float(h0));
        __nv_bfloat16 l1 = __float2bfloat16(v.y - __bfloat162float(h1));
        __nv_bfloat16 l2 = __float2bfloat16(v.z - __bfloat162float(h2));
        __nv_bfloat16 l3 = __float2bfloat16(v.w - __bfloat162float(h3));
        __nv_bfloat162 hv01, hv23, lv01, lv23;
        hv01.x = h0; hv01.y = h1; hv23.x = h2; hv23.y = h3;
        lv01.x = l0; lv01.y = l1; lv23.x = l2; lv23.y = l3;
        uint2 hp, lp;
        hp.x = *(uint32_t*)&hv01; hp.y = *(uint32_t*)&hv23;
        lp.x = *(uint32_t*)&lv01; lp.y = *(uint32_t*)&lv23;
        *(uint2*)(smem + bufoff + OFF_AH + row * 80 + c4 * 8) = hp;
        *(uint2*)(smem + bufoff + OFF_AL + row * 80 + c4 * 8) = lp;
    }
    const int row = tid >> 2, seg = tid & 3;
    *(uint4*)(smem + bufoff + OFF_BH + row * 80 + seg * 16) = st.bh;
    *(uint4*)(smem + bufoff + OFF_BL + row * 80 + seg * 16) = st.bl;
}

__global__ void __launch_bounds__(512, 1) k_gemm_mma(
        const float* __restrict__ states,
        const float* __restrict__ bk, const float* __restrict__ We_k) {
    extern __shared__ char smem[];
    const uint32_t sbase = smem_u32(smem);
    const int tid = threadIdx.x;
    const int wid = tid >> 5;
    const int lid = tid & 31;
    const int n_blk = blockIdx.x;   // 0..7
    const int m_blk = blockIdx.y;   // 0..255

    const int wm = wid & 3, wn = wid >> 2;
    const int m0 = wm * 32, n0 = wn * 32;

    // ldmatrix lane addressing
    const int a_r  = (lid & 7) + ((lid >> 3) & 1) * 8;
    const int a_cs = (lid >> 4) * 16;
    const int b_r  = (lid & 7) + (lid >> 4) * 8;   // half selects fn pair row
    const int b_ks = ((lid >> 3) & 1) * 16;

    const float* A = states + (size_t)m_blk * 128 * DIM;
    const __nv_bfloat16* Bh = g_wkT_hi + (size_t)n_blk * 128 * DIM;
    const __nv_bfloat16* Bl = g_wkT_lo + (size_t)n_blk * 128 * DIM;

    float acc[2][4][4];
    #pragma unroll
    for (int i = 0; i < 2; i++)
        #pragma unroll
        for (int j = 0; j < 4; j++)
            #pragma unroll
            for (int c = 0; c < 4; c++) acc[i][j][c] = 0.f;

    Stage st;
    ld_stage(st, A, Bh, Bl, 0, tid);
    st_stage(st, smem, 0, tid);
    ld_stage(st, A, Bh, Bl, 32, tid);
    __syncthreads();

    for (int s = 0; s < 32; s++) {
        const uint32_t ab = sbase + (uint32_t)(s & 1) * BUF_SZ;
        #pragma unroll
        for (int kk = 0; kk < 2; kk++) {
            const int kb = kk * 32;   // byte offset of k-step (16 bf16)
            uint32_t ah[2][4], al[2][4], bh[4][2], bl[4][2];
            #pragma unroll
            for (int fm = 0; fm < 2; fm++) {
                const uint32_t aoff = (uint32_t)((m0 + fm * 16 + a_r) * 80 + kb + a_cs);
                LDMX4(ah[fm][0], ah[fm][1], ah[fm][2], ah[fm][3], ab + OFF_AH + aoff);
                LDMX4(al[fm][0], al[fm][1], al[fm][2], al[fm][3], ab + OFF_AL + aoff);
            }
            #pragma unroll
            for (int q = 0; q < 2; q++) {
                const uint32_t boff = (uint32_t)((n0 + q * 16 + b_r) * 80 + kb + b_ks);
                LDMX4(bh[2 * q][0], bh[2 * q][1], bh[2 * q + 1][0], bh[2 * q + 1][1],
                      ab + OFF_BH + boff);
                LDMX4(bl[2 * q][0], bl[2 * q][1], bl[2 * q + 1][0], bl[2 * q + 1][1],
                      ab + OFF_BL + boff);
            }
            #pragma unroll
            for (int fm = 0; fm < 2; fm++)
                #pragma unroll
                for (int fn = 0; fn < 4; fn++) {
                    MMA16816(acc[fm][fn], ah[fm], bh[fn][0], bh[fn][1]);
                    MMA16816(acc[fm][fn], ah[fm], bl[fn][0], bl[fn][1]);
                    MMA16816(acc[fm][fn], al[fm], bh[fn][0], bh[fn][1]);
                }
        }
        if (s < 31) {
            __syncthreads();
            st_stage(st, smem, (uint32_t)((s + 1) & 1) * BUF_SZ, tid);
            if (s < 30) ld_stage(st, A, Bh, Bl, (s + 2) * 32, tid);
            __syncthreads();
        }
    }

    // Fused epilogue: tanh(relu(c + bk)) * We reduced over this 128-N tile
    float bkv[4][2], wev[4][2];
    #pragma unroll
    for (int fn = 0; fn < 4; fn++)
        #pragma unroll
        for (int j = 0; j < 2; j++) {
            const int n = n_blk * 128 + n0 + fn * 8 + (lid & 3) * 2 + j;
            bkv[fn][j] = bk[n];
            wev[fn][j] = We_k[n];
        }

    float* sred = (float*)(smem + RED_OFF);
    #pragma unroll
    for (int fm = 0; fm < 2; fm++)
        #pragma unroll
        for (int ch = 0; ch < 2; ch++) {
            float p = 0.f;
            #pragma unroll
            for (int fn = 0; fn < 4; fn++)
                #pragma unroll
                for (int j = 0; j < 2; j++) {
                    float v = acc[fm][fn][ch * 2 + j] + bkv[fn][j];
                    v = fmaxf(v, 0.f);
                    p = fmaf(tanhf(v), wev[fn][j], p);
                }
            p += __shfl_down_sync(0xffffffffu, p, 1, 4);
            p += __shfl_down_sync(0xffffffffu, p, 2, 4);
            if ((lid & 3) == 0)
                sred[wn * 128 + m0 + fm * 16 + ch * 8 + (lid >> 2)] = p;
        }
    __syncthreads();
    if (tid < 128) {
        const float e = sred[tid] + sred[128 + tid] + sred[256 + tid] + sred[384 + tid];
        g_ek_part[n_blk * M_TOT + m_blk * 128 + tid] = e;
    }
}

// ---------------------------------------------------------------------------
// softmax over s
// ---------------------------------------------------------------------------
__global__ void __launch_bounds__(256) k_softmax(
        const float* __restrict__ be, float* __restrict__ out_w) {
    const int b = blockIdx.x;
    const int tid = threadIdx.x;
    const float base = g_eq_part[b * 4 + 0] + g_eq_part[b * 4 + 1] +
                       g_eq_part[b * 4 + 2] + g_eq_part[b * 4 + 3] + be[0];
    float e[8];
    float lmax = -1e30f;
    #pragma unroll
    for (int r = 0; r < 8; r++) {
        const int s = r * 256 + tid;
        float v = base;
        #pragma unroll
        for (int p = 0; p < NSPLIT; p++)
            v += g_ek_part[p * M_TOT + b * SLEN + s];
        e[r] = v;
        lmax = fmaxf(lmax, v);
    }
    __shared__ float red[256];
    red[tid] = lmax; __syncthreads();
    for (int s = 128; s > 0; s >>= 1) {
        if (tid < s) red[tid] = fmaxf(red[tid], red[tid + s]);
        __syncthreads();
    }
    const float gmax = red[0];
    __syncthreads();
    float lsum = 0.f;
    #pragma unroll
    for (int r = 0; r < 8; r++) {
        e[r] = expf(e[r] - gmax);
        lsum += e[r];
    }
    red[tid] = lsum; __syncthreads();
    for (int s = 128; s > 0; s >>= 1) {
        if (tid < s) red[tid] += red[tid + s];
        __syncthreads();
    }
    const float inv = 1.f / red[0];
    #pragma unroll
    for (int r = 0; r < 8; r++)
        out_w[b * SLEN + r * 256 + tid] = e[r] * inv;
}

// ---------------------------------------------------------------------------
// attn partials + reduce
// ---------------------------------------------------------------------------
__global__ void __launch_bounds__(256) k_attn_part(
        const float* __restrict__ states, const float* __restrict__ w) {
    const int sc = blockIdx.x;   // 0..31
    const int b  = blockIdx.y;   // 0..15
    const int tid = threadIdx.x;
    const float4* st4 = (const float4*)states;
    float4 acc = make_float4(0.f, 0.f, 0.f, 0.f);
    const int s0 = sc * 64;
    #pragma unroll 4
    for (int sl = 0; sl < 64; sl++) {
        const int s = s0 + sl;
        const float wv = w[b * SLEN + s];
        const float4 v = st4[(size_t)(b * SLEN + s) * 256 + tid];
        acc.x = fmaf(wv, v.x, acc.x);
        acc.y = fmaf(wv, v.y, acc.y);
        acc.z = fmaf(wv, v.z, acc.z);
        acc.w = fmaf(wv, v.w, acc.w);
    }
    *(float4*)(g_attn_part + (size_t)(sc * BS + b) * DIM + tid * 4) = acc;
}

__global__ void __launch_bounds__(256) k_attn_reduce(float* __restrict__ out_attn) {
    const int idx = blockIdx.x * 256 + threadIdx.x;
    const int b = idx >> 10;
    const int d = idx & 1023;
    float s = 0.f;
    #pragma unroll
    for (int p = 0; p < 32; p++)
        s += g_attn_part[(size_t)(p * BS + b) * DIM + d];
    out_attn[idx] = s;
}

// ---------------------------------------------------------------------------
extern "C" void kernel_launch(void* const* d_in, const int* in_sizes, int n_in,
                              void* d_out, int out_size) {
    const float* query  = (const float*)d_in[0];
    const float* states = (const float*)d_in[1];
    const float* Wq     = (const float*)d_in[2];
    const float* bq     = (const float*)d_in[3];
    const float* Wk     = (const float*)d_in[4];
    const float* bk     = (const float*)d_in[5];
    const float* We     = (const float*)d_in[6];
    const float* be     = (const float*)d_in[7];

    float* out      = (float*)d_out;
    float* out_w    = out;                 // attn_weights (16, 2048)
    float* out_attn = out + BS * SLEN;     // attn         (16, 1024)

    static int smem_set = 0;
    if (!smem_set) {
        cudaFuncSetAttribute(k_gemm_mma,
                             cudaFuncAttributeMaxDynamicSharedMemorySize,
                             GEMM_SMEM);
        smem_set = 1;
    }

    k_convert_wkT<<<dim3(32, 32), dim3(32, 8)>>>(Wk);
    k_qenergy<<<dim3(BS, 4), 256>>>(query, Wq, bq, We);
    k_gemm_mma<<<dim3(NSPLIT, M_TOT / 128), 512, GEMM_SMEM>>>(states, bk, We + DIM);
    k_softmax<<<BS, 256>>>(be, out_w);
    k_attn_part<<<dim3(32, BS), 256>>>(states, out_w);
    k_attn_reduce<<<BS * DIM / 256, 256>>>(out_attn);
}